// round 8
// baseline (speedup 1.0000x reference)
#include <cuda_runtime.h>
#include <cuda_fp16.h>
#include <cstdint>

// ---------------- problem constants ----------------
#define N_IMG   32
#define C_IN    256
#define HW      64
#define K_OUT   256
#define X_ELEMS (N_IMG * C_IN * HW * HW)          // 33554432
#define W_ELEMS (K_OUT * C_IN * 9)                // 589824
#define NWBLK   (W_ELEMS / 16)                    // 36864
#define NTILE   32
#define TILES_PER_IMG (NTILE * NTILE)             // 1024
#define DT_POS_STRIDE ((size_t)N_IMG * TILES_PER_IMG * C_IN)   // 8388608

// ---------------- scratch ----------------
__device__ uint8_t g_xq[X_ELEMS];                     // NHWC fp8 (exact quantized)
__device__ uint8_t g_wq2[9 * K_OUT * C_IN];           // [rs][k][c] fp8 (exact)
__device__ __half  g_gt[16 * K_OUT * C_IN];           // winograd weights fp16
__device__ __half  g_dt[16ull * N_IMG * TILES_PER_IMG * C_IN]; // winograd data fp16

// ---------------- fp8 helpers ----------------
__device__ __forceinline__ uint16_t pack_e4m3_x2(float lo, float hi) {
    uint16_t r;
    asm volatile("cvt.rn.satfinite.e4m3x2.f32 %0, %1, %2;" : "=h"(r) : "f"(hi), "f"(lo));
    return r;
}
__device__ __forceinline__ uint8_t f32_to_e4m3(float v) {
    uint16_t r;
    asm volatile("cvt.rn.satfinite.e4m3x2.f32 %0, %1, %2;" : "=h"(r) : "f"(0.0f), "f"(v));
    return (uint8_t)(r & 0xFF);
}
__device__ __forceinline__ float e4m3_to_f32(uint8_t b) {
    uint16_t s = b;
    uint32_t h2;
    asm("cvt.rn.f16x2.e4m3x2 %0, %1;" : "=r"(h2) : "h"(s));
    __half lo = __ushort_as_half((uint16_t)(h2 & 0xFFFF));
    return __half2float(lo);
}

// ---------------- fake-quant core (exact pow2 scale + RTN E2M1) ----------------
__device__ __forceinline__ void quant16f(const float* __restrict__ v,
                                         float* __restrict__ q) {
    float amax = 0.0f;
#pragma unroll
    for (int i = 0; i < 16; ++i) amax = fmaxf(amax, fabsf(v[i]));
    float scale = 1.0f;
    if (amax > 0.0f) {
        float y = fmaxf(amax, 1e-30f) / 6.0f;
        int e;
        float m = frexpf(y, &e);
        scale = ldexpf(1.0f, (m == 0.5f) ? (e - 1) : e);
    }
    float inv = 1.0f / scale;
#pragma unroll
    for (int i = 0; i < 16; ++i) {
        float u = v[i] * inv;
        float a = fabsf(u);
        float g;
        if      (a < 0.25f) g = 0.0f;
        else if (a < 0.75f) g = 0.5f;
        else if (a < 1.25f) g = 1.0f;
        else if (a < 1.75f) g = 1.5f;
        else if (a < 2.5f)  g = 2.0f;
        else if (a < 3.5f)  g = 3.0f;
        else if (a < 5.0f)  g = 4.0f;
        else                g = 6.0f;
        q[i] = copysignf(g, u) * scale;     // exact in e4m3
    }
}

// ---------------- x quant -> NHWC fp8 (proven) ----------------
__global__ void __launch_bounds__(256)
quant_x_nhwc(const float* __restrict__ x, uint8_t* __restrict__ xq) {
    __shared__ uint16_t buf[64][136];
    const int n = blockIdx.x;
    const int h = blockIdx.y;
    const int t = threadIdx.x;
    const int cp  = t & 127;
    const int wb0 = t >> 7;

#pragma unroll
    for (int wbi = 0; wbi < 2; ++wbi) {
        int wb = wb0 + wbi * 2;
        const float* base = x + (((size_t)n * C_IN + 2 * cp) * HW + h) * HW + wb * 16;
        const float4* p0 = reinterpret_cast<const float4*>(base);
        const float4* p1 = reinterpret_cast<const float4*>(base + (size_t)HW * HW);
        float v0[16], v1[16];
#pragma unroll
        for (int i = 0; i < 4; ++i) {
            float4 a = p0[i];
            v0[i * 4 + 0] = a.x; v0[i * 4 + 1] = a.y; v0[i * 4 + 2] = a.z; v0[i * 4 + 3] = a.w;
            float4 b = p1[i];
            v1[i * 4 + 0] = b.x; v1[i * 4 + 1] = b.y; v1[i * 4 + 2] = b.z; v1[i * 4 + 3] = b.w;
        }
        float q0[16], q1[16];
        quant16f(v0, q0);
        quant16f(v1, q1);
#pragma unroll
        for (int j = 0; j < 16; ++j)
            buf[wb * 16 + j][cp] = pack_e4m3_x2(q0[j], q1[j]);
    }
    __syncthreads();

    uint8_t* orow = xq + (((size_t)n * HW + h) * HW) * C_IN;
#pragma unroll
    for (int i = 0; i < 4; ++i) {
        int idx = t + 256 * i;
        int p   = idx >> 4;
        int qd  = idx & 15;
        uint4 val = *reinterpret_cast<const uint4*>(&buf[p][qd * 8]);
        *reinterpret_cast<uint4*>(orow + (size_t)p * C_IN + qd * 16) = val;
    }
}

// ---------------- w quant + repack -> [rs][k][c] fp8 (proven) ----------------
__global__ void quant_w_repack(const float* __restrict__ w,
                               uint8_t* __restrict__ wq2) {
    int b = blockIdx.x * blockDim.x + threadIdx.x;
    if (b >= NWBLK) return;
    const float4* src = reinterpret_cast<const float4*>(w) + (size_t)b * 4;
    float4 t0 = src[0], t1 = src[1], t2 = src[2], t3 = src[3];
    float v[16] = {t0.x, t0.y, t0.z, t0.w, t1.x, t1.y, t1.z, t1.w,
                   t2.x, t2.y, t2.z, t2.w, t3.x, t3.y, t3.z, t3.w};
    float q[16];
    quant16f(v, q);
#pragma unroll
    for (int i = 0; i < 16; ++i) {
        int f  = b * 16 + i;
        int k  = f / 2304;
        int r2 = f - k * 2304;
        int c  = r2 / 9;
        int rs = r2 - c * 9;
        wq2[((size_t)rs * K_OUT + k) * C_IN + c] = f32_to_e4m3(q[i]);
    }
}

// ---------------- winograd weight transform: G w G^T -> gt[pos][k][c] fp16 ----
__global__ void __launch_bounds__(256)
wg_transform(const uint8_t* __restrict__ wq2, __half* __restrict__ gt) {
    int k = blockIdx.x;
    int c = threadIdx.x;
    float w9[9];
#pragma unroll
    for (int rs = 0; rs < 9; ++rs)
        w9[rs] = e4m3_to_f32(wq2[((size_t)rs * K_OUT + k) * C_IN + c]);
    float a[4][3];
#pragma unroll
    for (int j = 0; j < 3; ++j) {
        float w0 = w9[0 * 3 + j], w1 = w9[1 * 3 + j], w2 = w9[2 * 3 + j];
        a[0][j] = w0;
        a[1][j] = 0.5f * (w0 + w1 + w2);
        a[2][j] = 0.5f * (w0 - w1 + w2);
        a[3][j] = w2;
    }
#pragma unroll
    for (int i = 0; i < 4; ++i) {
        float u0 = a[i][0], u1 = a[i][1], u2 = a[i][2];
        float u[4] = {u0, 0.5f * (u0 + u1 + u2), 0.5f * (u0 - u1 + u2), u2};
#pragma unroll
        for (int j = 0; j < 4; ++j)
            gt[((size_t)(i * 4 + j) * K_OUT + k) * C_IN + c] = __float2half(u[j]);
    }
}

// ---------------- cp.async helpers ----------------
__device__ __forceinline__ void cp_async16(void* dst, const void* src, bool pred) {
    uint32_t d = (uint32_t)__cvta_generic_to_shared(dst);
    int sz = pred ? 16 : 0;
    asm volatile("cp.async.cg.shared.global [%0], [%1], 16, %2;\n"
                 :: "r"(d), "l"(src), "r"(sz));
}
__device__ __forceinline__ void cp_commit() {
    asm volatile("cp.async.commit_group;\n");
}
template <int N>
__device__ __forceinline__ void cp_wait() {
    asm volatile("cp.async.wait_group %0;\n" :: "n"(N));
}

// ---------------- winograd data transform: B^T d B -> dt[pos][tile][c] fp16 ---
// grid (n=32, th=32), 256 threads, dynamic smem 64KB: sx[4][64][256] fp8
__global__ void __launch_bounds__(256)
dt_transform(const uint8_t* __restrict__ xq, __half* __restrict__ dt) {
    extern __shared__ uint8_t sx[];
    const int n  = blockIdx.x;
    const int th = blockIdx.y;
    const int t  = threadIdx.x;

#pragma unroll
    for (int i = 0; i < 16; ++i) {
        int idx = t + 256 * i;            // 0..4095
        int h1  = idx >> 10;              // 0..3
        int rem = idx & 1023;
        int w   = rem >> 4;               // 0..63
        int cq  = rem & 15;               // 16B quad of c
        int gh  = th * 2 - 1 + h1;
        bool ok = (unsigned)gh < (unsigned)HW;
        cp_async16(sx + ((size_t)h1 * 64 + w) * 256 + cq * 16,
                   xq + (((size_t)n * HW + (ok ? gh : 0)) * HW + w) * C_IN + cq * 16, ok);
    }
    cp_commit();
    cp_wait<0>();
    __syncthreads();

    const int cp  = t & 127;              // channel pair
    const int twh = t >> 7;               // 0..1
    const __half2 zero = __floats2half2_rn(0.f, 0.f);

#pragma unroll 1
    for (int j = 0; j < 16; ++j) {
        int tw = j * 2 + twh;
        __half2 d[4][4];
#pragma unroll
        for (int wi = 0; wi < 4; ++wi) {
            int w = 2 * tw - 1 + wi;
            bool ok = (unsigned)w < (unsigned)HW;
#pragma unroll
            for (int h1 = 0; h1 < 4; ++h1) {
                if (ok) {
                    uint16_t u = *reinterpret_cast<const uint16_t*>(
                        sx + ((size_t)h1 * 64 + w) * 256 + 2 * cp);
                    uint32_t h2;
                    asm("cvt.rn.f16x2.e4m3x2 %0, %1;" : "=r"(h2) : "h"(u));
                    d[h1][wi] = *reinterpret_cast<__half2*>(&h2);
                } else {
                    d[h1][wi] = zero;
                }
            }
        }
        __half2 e[4][4];
#pragma unroll
        for (int h1 = 0; h1 < 4; ++h1) {
            e[h1][0] = __hsub2(d[h1][0], d[h1][2]);
            e[h1][1] = __hadd2(d[h1][1], d[h1][2]);
            e[h1][2] = __hsub2(d[h1][2], d[h1][1]);
            e[h1][3] = __hsub2(d[h1][1], d[h1][3]);
        }
        size_t tb = ((size_t)n * TILES_PER_IMG + th * NTILE + tw) * C_IN + 2 * cp;
#pragma unroll
        for (int jj = 0; jj < 4; ++jj) {
            __half2 D[4];
            D[0] = __hsub2(e[0][jj], e[2][jj]);
            D[1] = __hadd2(e[1][jj], e[2][jj]);
            D[2] = __hsub2(e[2][jj], e[1][jj]);
            D[3] = __hsub2(e[1][jj], e[3][jj]);
#pragma unroll
            for (int ii = 0; ii < 4; ++ii)
                *reinterpret_cast<uint32_t*>(&dt[(size_t)(ii * 4 + jj) * DT_POS_STRIDE + tb]) =
                    *reinterpret_cast<uint32_t*>(&D[ii]);
        }
    }
}

// ---------------- ldsm / mma ----------------
__device__ __forceinline__ void ldsm_x4(uint32_t addr, uint32_t& r0, uint32_t& r1,
                                        uint32_t& r2, uint32_t& r3) {
    asm volatile("ldmatrix.sync.aligned.m8n8.x4.shared.b16 {%0,%1,%2,%3}, [%4];"
                 : "=r"(r0), "=r"(r1), "=r"(r2), "=r"(r3) : "r"(addr));
}
__device__ __forceinline__ void ldsm_x2(uint32_t addr, uint32_t& r0, uint32_t& r1) {
    asm volatile("ldmatrix.sync.aligned.m8n8.x2.shared.b16 {%0,%1}, [%2];"
                 : "=r"(r0), "=r"(r1) : "r"(addr));
}
__device__ __forceinline__ void mma16816f16(float* d, const uint32_t* a,
                                            uint32_t b0, uint32_t b1) {
    asm volatile("mma.sync.aligned.m16n8k16.row.col.f32.f16.f16.f32 "
                 "{%0,%1,%2,%3}, {%4,%5,%6,%7}, {%8,%9}, {%0,%1,%2,%3};"
                 : "+f"(d[0]), "+f"(d[1]), "+f"(d[2]), "+f"(d[3])
                 : "r"(a[0]), "r"(a[1]), "r"(a[2]), "r"(a[3]), "r"(b0), "r"(b1));
}

// ---------------- winograd GEMM + inverse transform ----------------
// CTA: 64 kout x 32 tiles x 16 positions. 8 warps: wm(2 k-halves) x wg(4 tw-groups).
// smem rows (pos,k)/(pos,tw) x 16c fp16 = 32B padded to 48B (conflict-free ldsm).
#define GA_ROWS 1024                    // 16 pos x 64 k
#define GB_ROWS 512                     // 16 pos x 32 tw
#define GSTAGE  ((GA_ROWS + GB_ROWS) * 48)   // 73728
#define GSMEM   (2 * GSTAGE)                 // 147456

__device__ __forceinline__ void gemm_stage(char* base,
                                           const __half* __restrict__ gt,
                                           const __half* __restrict__ dt,
                                           int kt, size_t tilebase, int cc, int t) {
#pragma unroll
    for (int i = 0; i < 12; ++i) {
        int idx  = t + 256 * i;          // 0..3071
        int rid  = idx >> 1;
        int half = idx & 1;
        const void* src;
        if (rid < GA_ROWS) {
            int pos = rid >> 6;
            int k   = rid & 63;
            src = gt + ((size_t)pos * K_OUT + kt * 64 + k) * C_IN + cc + half * 8;
        } else {
            int r2  = rid - GA_ROWS;
            int pos = r2 >> 5;
            int tw  = r2 & 31;
            src = dt + (size_t)pos * DT_POS_STRIDE + tilebase + (size_t)tw * C_IN
                     + cc + half * 8;
        }
        cp_async16(base + rid * 48 + half * 16, src, true);
    }
}

__global__ void __launch_bounds__(256, 1)
wino_gemm(const __half* __restrict__ gt, const __half* __restrict__ dt,
          float* __restrict__ out) {
    extern __shared__ char smem[];
    const int kt = blockIdx.x;           // 0..3 (fastest: L2 reuse of dt tile)
    const int th = blockIdx.y;           // 0..31
    const int n  = blockIdx.z;           // 0..31
    const int t    = threadIdx.x;
    const int lane = t & 31;
    const int warp = t >> 5;
    const int wm   = warp & 1;           // k half (32 k)
    const int wg   = warp >> 1;          // tw group (8 tw)

    const size_t tilebase = ((size_t)n * TILES_PER_IMG + th * NTILE) * C_IN;

    float acc[16][2][4];
#pragma unroll
    for (int p = 0; p < 16; ++p)
#pragma unroll
        for (int m = 0; m < 2; ++m)
#pragma unroll
            for (int v = 0; v < 4; ++v) acc[p][m][v] = 0.0f;

    gemm_stage(smem, gt, dt, kt, tilebase, 0, t);
    cp_commit();

    const uint32_t su = (uint32_t)__cvta_generic_to_shared(smem);
    const int a_off = (lane & 15) * 48 + (lane >> 4) * 16;
    const int b_off = (lane & 7) * 48 + ((lane >> 3) & 1) * 16;

#pragma unroll 1
    for (int it = 0; it < 16; ++it) {
        int cur = it & 1;
        if (it + 1 < 16) {
            gemm_stage(smem + (cur ^ 1) * GSTAGE, gt, dt, kt, tilebase,
                       (it + 1) * 16, t);
            cp_commit();
            cp_wait<1>();
        } else {
            cp_wait<0>();
        }
        __syncthreads();

        const uint32_t sA = su + cur * GSTAGE;
        const uint32_t sB = sA + GA_ROWS * 48;
#pragma unroll
        for (int pos = 0; pos < 16; ++pos) {
            uint32_t a0[4], a1[4], b0, b1;
            ldsm_x4(sA + (pos * 64 + wm * 32) * 48 + a_off, a0[0], a0[1], a0[2], a0[3]);
            ldsm_x4(sA + (pos * 64 + wm * 32 + 16) * 48 + a_off, a1[0], a1[1], a1[2], a1[3]);
            ldsm_x2(sB + (pos * 32 + wg * 8) * 48 + b_off, b0, b1);
            mma16816f16(acc[pos][0], a0, b0, b1);
            mma16816f16(acc[pos][1], a1, b0, b1);
        }
        __syncthreads();
    }

    // epilogue: in-register inverse transform y = A^T M A, then store 2x2 outputs
    const int g2 = lane >> 2;
    const int tc = lane & 3;
#pragma unroll
    for (int mg = 0; mg < 2; ++mg) {
#pragma unroll
        for (int rs2 = 0; rs2 < 2; ++rs2) {
            int k = kt * 64 + wm * 32 + mg * 16 + g2 + rs2 * 8;
#pragma unroll
            for (int ts2 = 0; ts2 < 2; ++ts2) {
                int tw = wg * 8 + 2 * tc + ts2;
                float m[16];
#pragma unroll
                for (int p = 0; p < 16; ++p) m[p] = acc[p][mg][rs2 * 2 + ts2];
                float z0[4], z1[4];
#pragma unroll
                for (int i = 0; i < 4; ++i) {
                    z0[i] = m[i * 4 + 0] + m[i * 4 + 1] + m[i * 4 + 2];
                    z1[i] = m[i * 4 + 1] - m[i * 4 + 2] - m[i * 4 + 3];
                }
                float y00 = z0[0] + z0[1] + z0[2];
                float y01 = z1[0] + z1[1] + z1[2];
                float y10 = z0[1] - z0[2] - z0[3];
                float y11 = z1[1] - z1[2] - z1[3];
                size_t ob = (((size_t)n * K_OUT + k) * HW + th * 2) * HW + tw * 2;
                *reinterpret_cast<float2*>(out + ob)      = make_float2(y00, y01);
                *reinterpret_cast<float2*>(out + ob + HW) = make_float2(y10, y11);
            }
        }
    }
}

// ---------------- launch ----------------
extern "C" void kernel_launch(void* const* d_in, const int* in_sizes, int n_in,
                              void* d_out, int out_size) {
    const float* x = (const float*)d_in[0];
    const float* w = (const float*)d_in[1];
    if (in_sizes[0] != X_ELEMS) {
        x = (const float*)d_in[1];
        w = (const float*)d_in[0];
    }

    void *xq_p, *wq_p, *gt_p, *dt_p;
    cudaGetSymbolAddress(&xq_p, g_xq);
    cudaGetSymbolAddress(&wq_p, g_wq2);
    cudaGetSymbolAddress(&gt_p, g_gt);
    cudaGetSymbolAddress(&dt_p, g_dt);
    uint8_t* xq  = (uint8_t*)xq_p;
    uint8_t* wq2 = (uint8_t*)wq_p;
    __half*  gt  = (__half*)gt_p;
    __half*  dt  = (__half*)dt_p;

    cudaFuncSetAttribute(dt_transform,
                         cudaFuncAttributeMaxDynamicSharedMemorySize, 65536);
    cudaFuncSetAttribute(wino_gemm,
                         cudaFuncAttributeMaxDynamicSharedMemorySize, GSMEM);

    quant_x_nhwc<<<dim3(N_IMG, HW), 256>>>(x, xq);
    quant_w_repack<<<(NWBLK + 255) / 256, 256>>>(w, wq2);
    wg_transform<<<K_OUT, C_IN>>>(wq2, gt);
    dt_transform<<<dim3(N_IMG, NTILE), 256, 65536>>>(xq, dt);
    wino_gemm<<<dim3(4, NTILE, N_IMG), 256, GSMEM>>>(gt, dt, (float*)d_out);
}